// round 14
// baseline (speedup 1.0000x reference)
#include <cuda_runtime.h>
#include <cuda_bf16.h>
#include <math.h>
#include <stdint.h>

#define SEQ_TXT 256
#define SEQ_IMG 2048
#define SEQ_TOT 2304
#define DMODEL  3072
#define NHEADS  24
#define DHEAD   128
#define QKVP    (3 * DMODEL)

typedef __nv_bfloat16 bf16;

// bf16 hi/lo pre-split operands (weights kept in natural [k][n] layout)
__device__ bf16 g_xh[SEQ_TOT * DMODEL],  g_xl[SEQ_TOT * DMODEL];
__device__ bf16 g_qh[SEQ_TOT * DMODEL],  g_ql[SEQ_TOT * DMODEL];
__device__ bf16 g_kh[SEQ_TOT * DMODEL],  g_kl[SEQ_TOT * DMODEL];
__device__ bf16 g_vh[SEQ_TOT * DMODEL],  g_vl[SEQ_TOT * DMODEL];   // [seq][d]
__device__ bf16 g_ath[SEQ_TOT * DMODEL], g_atl[SEQ_TOT * DMODEL];
__device__ bf16 g_wh[8][DMODEL * (long)DMODEL];
__device__ bf16 g_wl[8][DMODEL * (long)DMODEL];

__device__ __forceinline__ void bsplit(float x, bf16& h, bf16& l) {
    h = __float2bfloat16_rn(x);
    l = __float2bfloat16_rn(x - __bfloat162float(h));
}
__device__ __forceinline__ uint32_t pack2(bf16 a, bf16 b) {
    __nv_bfloat162 t = __halves2bfloat162(a, b);
    return *(uint32_t*)&t;
}
__device__ __forceinline__ uint32_t cvta_s(const void* p) {
    return (uint32_t)__cvta_generic_to_shared(p);
}

#define MMA_BF16(CV, AV, BV) \
    asm volatile( \
        "mma.sync.aligned.m16n8k16.row.col.f32.bf16.bf16.f32 " \
        "{%0,%1,%2,%3}, {%4,%5,%6,%7}, {%8,%9}, {%0,%1,%2,%3};" \
        : "+f"((CV)[0]), "+f"((CV)[1]), "+f"((CV)[2]), "+f"((CV)[3]) \
        : "r"((AV)[0]), "r"((AV)[1]), "r"((AV)[2]), "r"((AV)[3]), \
          "r"((BV)[0]), "r"((BV)[1]))

#define LDSM_X4(R, ADDR) \
    asm volatile("ldmatrix.sync.aligned.m8n8.x4.shared.b16 {%0,%1,%2,%3}, [%4];" \
        : "=r"((R)[0]), "=r"((R)[1]), "=r"((R)[2]), "=r"((R)[3]) : "r"(ADDR))

#define LDSM_X4_T(R, ADDR) \
    asm volatile("ldmatrix.sync.aligned.m8n8.x4.trans.shared.b16 {%0,%1,%2,%3}, [%4];" \
        : "=r"((R)[0]), "=r"((R)[1]), "=r"((R)[2]), "=r"((R)[3]) : "r"(ADDR))

#define CP_ASYNC16(dst, src) \
    asm volatile("cp.async.cg.shared.global [%0], [%1], 16;" \
        :: "r"(dst), "l"(src) : "memory")
#define CP_COMMIT() asm volatile("cp.async.commit_group;" ::: "memory")
#define CP_WAIT(N)  asm volatile("cp.async.wait_group %0;" :: "n"(N) : "memory")

#define WSTRIDE 20

// ---- M=64 GEMM tile geometry ----
// A tile: 64 rows x 20 words (per hi/lo); B tile: 32 k-rows x 68 words.
#define ATWB64 (64 * WSTRIDE * 4)       // 5120
#define BTWB   (32 * 68 * 4)            // 8704
#define STAGE64 (2 * ATWB64 + 2 * BTWB) // 27648
#define SMEMB64 (2 * STAGE64)           // 55296
#define B64_HI (2 * ATWB64)
#define B64_LO (2 * ATWB64 + BTWB)

// term-outermost: all hh, then hl, then lh (per-acc order preserved)
#define MMA_BLOCK64(ACC, AH, AL, BH, BL) \
    do { \
        _Pragma("unroll") \
        for (int mt = 0; mt < 2; mt++) \
            _Pragma("unroll") \
            for (int nt = 0; nt < 4; nt++) \
                MMA_BF16(ACC[mt][nt], AH[mt], (&BH[nt >> 1][(nt & 1) * 2])); \
        _Pragma("unroll") \
        for (int mt = 0; mt < 2; mt++) \
            _Pragma("unroll") \
            for (int nt = 0; nt < 4; nt++) \
                MMA_BF16(ACC[mt][nt], AH[mt], (&BL[nt >> 1][(nt & 1) * 2])); \
        _Pragma("unroll") \
        for (int mt = 0; mt < 2; mt++) \
            _Pragma("unroll") \
            for (int nt = 0; nt < 4; nt++) \
                MMA_BF16(ACC[mt][nt], AL[mt], (&BH[nt >> 1][(nt & 1) * 2])); \
    } while (0)

// ===========================================================================
// QKV GEMM (64x128 tiles) + fused epilogue.
// Warps: 2(m) x 4(n); warp tile 32x32.
// ===========================================================================
__global__ __launch_bounds__(256, 2) void qkv_gemm(
    const bf16* __restrict__ Ahi, const bf16* __restrict__ Alo,
    const bf16* __restrict__ Wh, const bf16* __restrict__ Wl,
    bf16* __restrict__ qh, bf16* __restrict__ ql,
    bf16* __restrict__ kh, bf16* __restrict__ kl,
    bf16* __restrict__ vh, bf16* __restrict__ vl,
    const float* __restrict__ gq, const float* __restrict__ gaq,
    const float* __restrict__ gk, const float* __restrict__ gak,
    const float* __restrict__ freqs, float qscale)
{
    extern __shared__ uint32_t sm[];
    __shared__ float red[2][8][4][4];

    const bool txt = (int)blockIdx.y < 4;          // rows 0..255 are txt
    const int sec  = blockIdx.x / 24;              // 0=q 1=k 2=v
    const int col0 = blockIdx.x * 128;
    const int nbase = col0 - sec * DMODEL;
    const long WSZ = (long)DMODEL * DMODEL;
    const bf16* Bh = Wh + (sec + (txt ? 3 : 0)) * WSZ;
    const bf16* Bl = Wl + (sec + (txt ? 3 : 0)) * WSZ;

    const int row0 = blockIdx.y * 64;

    const int tid = threadIdx.x;
    const int lane = tid & 31, wid = tid >> 5;
    const int m_off = (wid & 1) * 32, n_off = (wid >> 1) * 32;
    const int lr = lane >> 2, lc = lane & 3;
    const int mg = wid & 1, gg = wid >> 1;

    const uint32_t sbase = cvta_s(sm);
    const uint32_t aoff = ((m_off + (lane & 15)) * WSTRIDE + ((lane >> 4) & 1) * 4) * 4;
    const uint32_t boff = (lane & 15) * 272 + (n_off + ((lane >> 4) & 1) * 8) * 2;
    const uint32_t MT_OFF = 16 * WSTRIDE * 4;

    const int pr = tid >> 2, pw = (tid & 3) * 4;   // A loader: 1 row per thread
    const int br = tid >> 4, bj = tid & 15;        // B loader

    auto issue = [&](int k0, int buf) {
        uint32_t sb = sbase + buf * STAGE64;
        {
            uint32_t so = (uint32_t)(pr * WSTRIDE + pw) * 4;
            long ro = (long)(row0 + pr) * DMODEL + k0 + pw * 2;
            CP_ASYNC16(sb + so,          Ahi + ro);
            CP_ASYNC16(sb + ATWB64 + so, Alo + ro);
        }
        #pragma unroll
        for (int p = 0; p < 2; p++) {
            int r = br + p * 16;
            uint32_t so = (uint32_t)(r * 68 + bj * 4) * 4;
            long co = (long)(k0 + r) * DMODEL + nbase + bj * 8;
            CP_ASYNC16(sb + B64_HI + so, Bh + co);
            CP_ASYNC16(sb + B64_LO + so, Bl + co);
        }
        CP_COMMIT();
    };

    issue(0, 0);

    float acc[2][4][4];
    #pragma unroll
    for (int mt = 0; mt < 2; mt++)
        #pragma unroll
        for (int nt = 0; nt < 4; nt++)
            #pragma unroll
            for (int i = 0; i < 4; i++) acc[mt][nt][i] = 0.0f;

    CP_WAIT(0);
    __syncthreads();

    const int nIter = DMODEL >> 5;
    for (int it = 0; it < nIter; ++it) {
        const int cur = it & 1;
        if (it + 1 < nIter) issue((it + 1) * 32, cur ^ 1);
        const uint32_t stg = sbase + cur * STAGE64;

        #pragma unroll
        for (int ks = 0; ks < 2; ks++) {
            uint32_t ah[2][4], al[2][4], bh[2][4], bl[2][4];
            #pragma unroll
            for (int mt = 0; mt < 2; mt++) {
                LDSM_X4(ah[mt], stg + aoff + mt * MT_OFF + ks * 32);
                LDSM_X4(al[mt], stg + ATWB64 + aoff + mt * MT_OFF + ks * 32);
            }
            #pragma unroll
            for (int p = 0; p < 2; p++) {
                LDSM_X4_T(bh[p], stg + B64_HI + boff + p * 32 + ks * 4352);
                LDSM_X4_T(bl[p], stg + B64_LO + boff + p * 32 + ks * 4352);
            }
            MMA_BLOCK64(acc, ah, al, bh, bl);
        }

        if (it + 1 < nIter) CP_WAIT(0);
        __syncthreads();
    }

    if (sec < 2) {
        // rmsnorm over d=128 spread across 4 n-warp-groups
        float ss4[4] = {0.f, 0.f, 0.f, 0.f};
        #pragma unroll
        for (int mt = 0; mt < 2; mt++)
            #pragma unroll
            for (int nt = 0; nt < 4; nt++)
                #pragma unroll
                for (int c = 0; c < 4; c++) {
                    float v = acc[mt][nt][c];
                    ss4[mt * 2 + (c >> 1)] += v * v;
                }
        #pragma unroll
        for (int s = 0; s < 4; s++) {
            ss4[s] += __shfl_xor_sync(0xffffffffu, ss4[s], 1);
            ss4[s] += __shfl_xor_sync(0xffffffffu, ss4[s], 2);
            if (lc == 0) red[mg][lr][s][gg] = ss4[s];
        }
        __syncthreads();

        float rn4[4];
        #pragma unroll
        for (int s = 0; s < 4; s++) {
            float tot = red[mg][lr][s][0] + red[mg][lr][s][1]
                      + red[mg][lr][s][2] + red[mg][lr][s][3];
            rn4[s] = rsqrtf(tot * (1.0f / 128.0f) + 1e-5f);
        }

        const float* g = (sec == 0) ? (txt ? gaq : gq) : (txt ? gak : gk);
        bf16* oh = (sec == 0) ? qh : kh;
        bf16* ol = (sec == 0) ? ql : kl;
        const float sc = (sec == 0) ? qscale : 1.0f;

        #pragma unroll
        for (int mt = 0; mt < 2; mt++) {
            int r0 = row0 + m_off + mt * 16 + lr;
            #pragma unroll
            for (int nt = 0; nt < 4; nt++) {
                int d = n_off + nt * 8 + lc * 2;
                float g0 = g[d], g1 = g[d + 1];
                {
                    float rn = rn4[mt * 2];
                    float x0 = acc[mt][nt][0] * rn * g0;
                    float x1 = acc[mt][nt][1] * rn * g1;
                    float4 fv = *(const float4*)(freqs + (long)r0 * 256 + (d >> 1) * 4);
                    float o0 = (fv.x * x0 + fv.y * x1) * sc;
                    float o1 = (fv.z * x0 + fv.w * x1) * sc;
                    bf16 h0, l0, h1, l1;
                    bsplit(o0, h0, l0); bsplit(o1, h1, l1);
                    long off = (long)r0 * DMODEL + nbase + d;
                    *(uint32_t*)(oh + off) = pack2(h0, h1);
                    *(uint32_t*)(ol + off) = pack2(l0, l1);
                }
                {
                    float rn = rn4[mt * 2 + 1];
                    float x0 = acc[mt][nt][2] * rn * g0;
                    float x1 = acc[mt][nt][3] * rn * g1;
                    float4 fv = *(const float4*)(freqs + (long)(r0 + 8) * 256 + (d >> 1) * 4);
                    float o0 = (fv.x * x0 + fv.y * x1) * sc;
                    float o1 = (fv.z * x0 + fv.w * x1) * sc;
                    bf16 h0, l0, h1, l1;
                    bsplit(o0, h0, l0); bsplit(o1, h1, l1);
                    long off = (long)(r0 + 8) * DMODEL + nbase + d;
                    *(uint32_t*)(oh + off) = pack2(h0, h1);
                    *(uint32_t*)(ol + off) = pack2(l0, l1);
                }
            }
        }
    } else {
        #pragma unroll
        for (int mt = 0; mt < 2; mt++) {
            int r0 = row0 + m_off + mt * 16 + lr;
            #pragma unroll
            for (int nt = 0; nt < 4; nt++) {
                int d = n_off + nt * 8 + lc * 2;
                bf16 h0, l0, h1, l1;
                bsplit(acc[mt][nt][0], h0, l0);
                bsplit(acc[mt][nt][1], h1, l1);
                long off = (long)r0 * DMODEL + nbase + d;
                *(uint32_t*)(vh + off) = pack2(h0, h1);
                *(uint32_t*)(vl + off) = pack2(l0, l1);
                bsplit(acc[mt][nt][2], h0, l0);
                bsplit(acc[mt][nt][3], h1, l1);
                off = (long)(r0 + 8) * DMODEL + nbase + d;
                *(uint32_t*)(vh + off) = pack2(h0, h1);
                *(uint32_t*)(vl + off) = pack2(l0, l1);
            }
        }
    }
}

// ===========================================================================
// Output-projection GEMM (64x128 tiles)
// ===========================================================================
__global__ __launch_bounds__(256, 2) void tgemm(
    const bf16* __restrict__ Ahi, const bf16* __restrict__ Alo,
    const bf16* __restrict__ Bhi, const bf16* __restrict__ Blo,
    const bf16* __restrict__ B2hi, const bf16* __restrict__ B2lo,
    float* __restrict__ C,
    const float* __restrict__ bias, const float* __restrict__ bias2)
{
    extern __shared__ uint32_t sm[];

    const bool txt = (int)blockIdx.y < 4;
    const bf16* Bh = txt ? B2hi : Bhi;
    const bf16* Bl = txt ? B2lo : Blo;
    const float* bptr = txt ? bias2 : bias;

    const int row0 = blockIdx.y * 64;
    const int col0 = blockIdx.x * 128;
    const int crow0 = txt ? (SEQ_IMG + row0) : (row0 - SEQ_TXT);

    const int tid = threadIdx.x;
    const int lane = tid & 31, wid = tid >> 5;
    const int m_off = (wid & 1) * 32, n_off = (wid >> 1) * 32;
    const int lr = lane >> 2, lc = lane & 3;

    const uint32_t sbase = cvta_s(sm);
    const uint32_t aoff = ((m_off + (lane & 15)) * WSTRIDE + ((lane >> 4) & 1) * 4) * 4;
    const uint32_t boff = (lane & 15) * 272 + (n_off + ((lane >> 4) & 1) * 8) * 2;
    const uint32_t MT_OFF = 16 * WSTRIDE * 4;

    const int pr = tid >> 2, pw = (tid & 3) * 4;
    const int br = tid >> 4, bj = tid & 15;

    auto issue = [&](int k0, int buf) {
        uint32_t sb = sbase + buf * STAGE64;
        {
            uint32_t so = (uint32_t)(pr * WSTRIDE + pw) * 4;
            long ro = (long)(row0 + pr) * DMODEL + k0 + pw * 2;
            CP_ASYNC16(sb + so,          Ahi + ro);
            CP_ASYNC16(sb + ATWB64 + so, Alo + ro);
        }
        #pragma unroll
        for (int p = 0; p < 2; p++) {
            int r = br + p * 16;
            uint32_t so = (uint32_t)(r * 68 + bj * 4) * 4;
            long co = (long)(k0 + r) * DMODEL + col0 + bj * 8;
            CP_ASYNC16(sb + B64_HI + so, Bh + co);
            CP_ASYNC16(sb + B64_LO + so, Bl + co);
        }
        CP_COMMIT();
    };

    issue(0, 0);

    float acc[2][4][4];
    #pragma unroll
    for (int mt = 0; mt < 2; mt++)
        #pragma unroll
        for (int nt = 0; nt < 4; nt++)
            #pragma unroll
            for (int i = 0; i < 4; i++) acc[mt][nt][i] = 0.0f;

    CP_WAIT(0);
    __syncthreads();

    const int nIter = DMODEL >> 5;
    for (int it = 0; it < nIter; ++it) {
        const int cur = it & 1;
        if (it + 1 < nIter) issue((it + 1) * 32, cur ^ 1);
        const uint32_t stg = sbase + cur * STAGE64;

        #pragma unroll
        for (int ks = 0; ks < 2; ks++) {
            uint32_t ah[2][4], al[2][4], bh[2][4], bl[2][4];
            #pragma unroll
            for (int mt = 0; mt < 2; mt++) {
                LDSM_X4(ah[mt], stg + aoff + mt * MT_OFF + ks * 32);
                LDSM_X4(al[mt], stg + ATWB64 + aoff + mt * MT_OFF + ks * 32);
            }
            #pragma unroll
            for (int p = 0; p < 2; p++) {
                LDSM_X4_T(bh[p], stg + B64_HI + boff + p * 32 + ks * 4352);
                LDSM_X4_T(bl[p], stg + B64_LO + boff + p * 32 + ks * 4352);
            }
            MMA_BLOCK64(acc, ah, al, bh, bl);
        }

        if (it + 1 < nIter) CP_WAIT(0);
        __syncthreads();
    }

    #pragma unroll
    for (int mt = 0; mt < 2; mt++) {
        #pragma unroll
        for (int nt = 0; nt < 4; nt++) {
            int r0 = crow0 + m_off + mt * 16 + lr;
            int cc = col0 + n_off + nt * 8 + lc * 2;
            float2 v0, v1;
            v0.x = acc[mt][nt][0] + bptr[cc];
            v0.y = acc[mt][nt][1] + bptr[cc + 1];
            v1.x = acc[mt][nt][2] + bptr[cc];
            v1.y = acc[mt][nt][3] + bptr[cc + 1];
            *(float2*)(C + (long)r0 * DMODEL + cc)       = v0;
            *(float2*)(C + (long)(r0 + 8) * DMODEL + cc) = v1;
        }
    }
}

// ===========================================================================
// Flash attention (unchanged from R13)
// ===========================================================================
#define FTW 8704
#define FTWB (FTW * 4)
#define FLASH_SMEM (6 * FTWB)

#define MMA_BLOCK(ACC, AH, AL, BH, BL) \
    do { \
        _Pragma("unroll") \
        for (int mt = 0; mt < 2; mt++) \
            _Pragma("unroll") \
            for (int nt = 0; nt < 8; nt++) \
                MMA_BF16(ACC[mt][nt], AH[mt], (&BH[nt >> 1][(nt & 1) * 2])); \
        _Pragma("unroll") \
        for (int mt = 0; mt < 2; mt++) \
            _Pragma("unroll") \
            for (int nt = 0; nt < 8; nt++) \
                MMA_BF16(ACC[mt][nt], AH[mt], (&BL[nt >> 1][(nt & 1) * 2])); \
        _Pragma("unroll") \
        for (int mt = 0; mt < 2; mt++) \
            _Pragma("unroll") \
            for (int nt = 0; nt < 8; nt++) \
                MMA_BF16(ACC[mt][nt], AL[mt], (&BH[nt >> 1][(nt & 1) * 2])); \
    } while (0)

__global__ __launch_bounds__(256, 1) void flash_kernel(
    const bf16* __restrict__ Qh, const bf16* __restrict__ Ql,
    const bf16* __restrict__ Kh, const bf16* __restrict__ Kl,
    const bf16* __restrict__ Vh, const bf16* __restrict__ Vl,
    bf16* __restrict__ Oh, bf16* __restrict__ Ol)
{
    extern __shared__ uint32_t sm[];
    __shared__ float red[4][8][4][2];

    const int h  = blockIdx.y;
    const int q0 = blockIdx.x * 128;
    const int tid = threadIdx.x;
    const int lane = tid & 31, wid = tid >> 5;
    const int m_off = (wid & 3) * 32, n_off = (wid >> 2) * 64;
    const int lr = lane >> 2, lc = lane & 3;
    const int mg = wid & 3, gg = wid >> 2;

    uint32_t* sPh = sm + 2 * FTW;
    uint32_t* sPl = sm + 3 * FTW;

    const uint32_t sbase = cvta_s(sm);
    const uint32_t aoff = ((m_off + (lane & 15)) * 68 + ((lane >> 4) & 1) * 4) * 4;
    const uint32_t boff = ((n_off + (lane & 7) + ((lane >> 4) & 1) * 8) * 68
                           + ((lane >> 3) & 1) * 4) * 4;
    const uint32_t voff = (lane & 15) * 272 + (n_off + ((lane >> 4) & 1) * 8) * 2;
    const uint32_t MT_OFF = 16 * 68 * 4;

    auto issue_tile = [&](uint32_t dhb, uint32_t dlb,
                          const bf16* gh, const bf16* gl,
                          int rs0, int cs0) {
        #pragma unroll
        for (int i = 0; i < 8; i++) {
            int idx = tid + 256 * i;
            int r = idx >> 4, u = idx & 15;
            long go = (long)(rs0 + r) * DMODEL + cs0 + u * 8;
            uint32_t so = (uint32_t)(r * 68 + u * 4) * 4;
            CP_ASYNC16(dhb + so, gh + go);
            CP_ASYNC16(dlb + so, gl + go);
        }
        CP_COMMIT();
    };

    issue_tile(sbase, sbase + FTWB, Qh, Ql, q0, h * DHEAD);

    float m_i[4], l_i[4], oacc[2][8][4];
    #pragma unroll
    for (int s = 0; s < 4; s++) { m_i[s] = -INFINITY; l_i[s] = 0.0f; }
    #pragma unroll
    for (int mt = 0; mt < 2; mt++)
        #pragma unroll
        for (int nt = 0; nt < 8; nt++)
            #pragma unroll
            for (int c = 0; c < 4; c++) oacc[mt][nt][c] = 0.0f;

    for (int kv = 0; kv < SEQ_TOT / 128; kv++) {
        const int kv0 = kv * 128;
        __syncthreads();
        issue_tile(sbase + 2 * FTWB, sbase + 3 * FTWB, Kh, Kl, kv0, h * DHEAD);
        issue_tile(sbase + 4 * FTWB, sbase + 5 * FTWB, Vh, Vl, kv0, h * DHEAD);
        CP_WAIT(1);
        __syncthreads();

        float sacc[2][8][4];
        #pragma unroll
        for (int mt = 0; mt < 2; mt++)
            #pragma unroll
            for (int nt = 0; nt < 8; nt++)
                #pragma unroll
                for (int c = 0; c < 4; c++) sacc[mt][nt][c] = 0.0f;

        #pragma unroll
        for (int ks = 0; ks < 8; ks++) {
            uint32_t ah[2][4], al[2][4], bh[4][4], bl[4][4];
            #pragma unroll
            for (int mt = 0; mt < 2; mt++) {
                LDSM_X4(ah[mt], sbase + aoff + mt * MT_OFF + ks * 32);
                LDSM_X4(al[mt], sbase + FTWB + aoff + mt * MT_OFF + ks * 32);
            }
            #pragma unroll
            for (int p = 0; p < 4; p++) {
                LDSM_X4(bh[p], sbase + 2 * FTWB + boff + p * MT_OFF + ks * 32);
                LDSM_X4(bl[p], sbase + 3 * FTWB + boff + p * MT_OFF + ks * 32);
            }
            MMA_BLOCK(sacc, ah, al, bh, bl);
        }

        float mx4[4];
        #pragma unroll
        for (int s = 0; s < 4; s++) {
            int mt = s >> 1, c0 = (s & 1) * 2;
            float mx = sacc[mt][0][c0];
            #pragma unroll
            for (int nt = 0; nt < 8; nt++) {
                mx = fmaxf(mx, sacc[mt][nt][c0]);
                mx = fmaxf(mx, sacc[mt][nt][c0 + 1]);
            }
            mx = fmaxf(mx, __shfl_xor_sync(0xffffffffu, mx, 1));
            mx = fmaxf(mx, __shfl_xor_sync(0xffffffffu, mx, 2));
            mx4[s] = mx;
            if (lc == 0) red[mg][lr][s][gg] = mx;
        }
        __syncthreads();

        float a4[4], mnew[4];
        #pragma unroll
        for (int s = 0; s < 4; s++) {
            mnew[s] = fmaxf(m_i[s], fmaxf(mx4[s], red[mg][lr][s][gg ^ 1]));
            a4[s] = __expf(m_i[s] - mnew[s]);
            m_i[s] = mnew[s];
            l_i[s] *= a4[s];
        }

        float rs4[4] = {0.f, 0.f, 0.f, 0.f};
        #pragma unroll
        for (int mt = 0; mt < 2; mt++)
            #pragma unroll
            for (int nt = 0; nt < 8; nt++)
                #pragma unroll
                for (int c = 0; c < 4; c++) {
                    int s = mt * 2 + (c >> 1);
                    float e = __expf(sacc[mt][nt][c] - mnew[s]);
                    sacc[mt][nt][c] = e;
                    rs4[s] += e;
                }
        #pragma unroll
        for (int s = 0; s < 4; s++) {
            rs4[s] += __shfl_xor_sync(0xffffffffu, rs4[s], 1);
            rs4[s] += __shfl_xor_sync(0xffffffffu, rs4[s], 2);
        }
        #pragma unroll
        for (int mt = 0; mt < 2; mt++)
            #pragma unroll
            for (int nt = 0; nt < 8; nt++) {
                oacc[mt][nt][0] *= a4[mt * 2];
                oacc[mt][nt][1] *= a4[mt * 2];
                oacc[mt][nt][2] *= a4[mt * 2 + 1];
                oacc[mt][nt][3] *= a4[mt * 2 + 1];
            }
        __syncthreads();

        #pragma unroll
        for (int s = 0; s < 4; s++)
            if (lc == 0) red[mg][lr][s][gg] = rs4[s];

        #pragma unroll
        for (int mt = 0; mt < 2; mt++)
            #pragma unroll
            for (int nt = 0; nt < 8; nt++) {
                int w = (n_off >> 1) + nt * 4 + lc;
                int o = (m_off + mt * 16 + lr) * 68 + w;
                bf16 h0, l0, h1, l1;
                bsplit(sacc[mt][nt][0], h0, l0);
                bsplit(sacc[mt][nt][1], h1, l1);
                sPh[o] = pack2(h0, h1); sPl[o] = pack2(l0, l1);
                bsplit(sacc[mt][nt][2], h0, l0);
                bsplit(sacc[mt][nt][3], h1, l1);
                sPh[o + 8 * 68] = pack2(h0, h1); sPl[o + 8 * 68] = pack2(l0, l1);
            }
        CP_WAIT(0);
        __syncthreads();

        #pragma unroll
        for (int s = 0; s < 4; s++)
            l_i[s] += rs4[s] + red[mg][lr][s][gg ^ 1];

        #pragma unroll
        for (int ks = 0; ks < 8; ks++) {
            uint32_t ah[2][4], al[2][4], bh[4][4], bl[4][4];
            #pragma unroll
            for (int mt = 0; mt < 2; mt++) {
                LDSM_X4(ah[mt], sbase + 2 * FTWB + aoff + mt * MT_OFF + ks * 32);
                LDSM_X4(al[mt], sbase + 3 * FTWB + aoff + mt * MT_OFF + ks * 32);
            }
            #pragma unroll
            for (int p = 0; p < 4; p++) {
                LDSM_X4_T(bh[p], sbase + 4 * FTWB + voff + p * 32 + ks * 4352);
                LDSM_X4_T(bl[p], sbase + 5 * FTWB + voff + p * 32 + ks * 4352);
            }
            MMA_BLOCK(oacc, ah, al, bh, bl);
        }
    }

    #pragma unroll
    for (int mt = 0; mt < 2; mt++) {
        float i0 = 1.0f / l_i[mt * 2];
        float i1 = 1.0f / l_i[mt * 2 + 1];
        #pragma unroll
        for (int nt = 0; nt < 8; nt++) {
            int col = h * DHEAD + n_off + nt * 8 + lc * 2;
            long r0 = q0 + m_off + mt * 16 + lr;
            bf16 h0, l0, h1, l1;
            bsplit(oacc[mt][nt][0] * i0, h0, l0);
            bsplit(oacc[mt][nt][1] * i0, h1, l1);
            *(uint32_t*)(Oh + r0 * DMODEL + col) = pack2(h0, h1);
            *(uint32_t*)(Ol + r0 * DMODEL + col) = pack2(l0, l1);
            bsplit(oacc[mt][nt][2] * i1, h0, l0);
            bsplit(oacc[mt][nt][3] * i1, h1, l1);
            *(uint32_t*)(Oh + (r0 + 8) * DMODEL + col) = pack2(h0, h1);
            *(uint32_t*)(Ol + (r0 + 8) * DMODEL + col) = pack2(l0, l1);
        }
    }
}

// ===========================================================================
// Prep: pure streaming hi/lo split (unchanged)
// ===========================================================================
__global__ __launch_bounds__(256) void prep_kernel(
    const float* __restrict__ hid, const float* __restrict__ enc,
    const float* W0, const float* W1, const float* W2, const float* W3,
    const float* W4, const float* W5, const float* W6, const float* W7,
    bf16* __restrict__ wh, bf16* __restrict__ wl,
    bf16* __restrict__ xh, bf16* __restrict__ xl)
{
    const int z = blockIdx.y;
    const int tid = threadIdx.x;
    const int NBLK = 1024;

    const float* src;
    bf16 *hi, *lo;
    int n4;
    if (z == 8) {
        n4 = SEQ_TOT * DMODEL / 4;
        src = nullptr; hi = xh; lo = xl;
    } else {
        n4 = DMODEL * DMODEL / 4;
        const float* Ws = W0;
        switch (z) {
            case 1: Ws = W1; break; case 2: Ws = W2; break; case 3: Ws = W3; break;
            case 4: Ws = W4; break; case 5: Ws = W5; break; case 6: Ws = W6; break;
            case 7: Ws = W7; break; default: break;
        }
        src = Ws;
        hi = wh + (long)z * DMODEL * DMODEL;
        lo = wl + (long)z * DMODEL * DMODEL;
    }

    const int TXT4 = SEQ_TXT * DMODEL / 4;
    for (int idx = blockIdx.x * 256 + tid; idx < n4; idx += NBLK * 256) {
        float4 v;
        if (z == 8)
            v = (idx < TXT4) ? ((const float4*)enc)[idx]
                             : ((const float4*)hid)[idx - TXT4];
        else
            v = ((const float4*)src)[idx];
        bf16 h0, l0, h1, l1, h2, l2, h3, l3;
        bsplit(v.x, h0, l0); bsplit(v.y, h1, l1);
        bsplit(v.z, h2, l2); bsplit(v.w, h3, l3);
        ((uint2*)hi)[idx] = make_uint2(pack2(h0, h1), pack2(h2, h3));
        ((uint2*)lo)[idx] = make_uint2(pack2(l0, l1), pack2(l2, l3));
    }
}

// ---------------------------------------------------------------------------
extern "C" void kernel_launch(void* const* d_in, const int* in_sizes, int n_in,
                              void* d_out, int out_size)
{
    const float* hid   = (const float*)d_in[0];
    const float* enc   = (const float*)d_in[1];
    const float* freqs = (const float*)d_in[2];
    const float* gq  = (const float*)d_in[9];
    const float* gk  = (const float*)d_in[10];
    const float* gaq = (const float*)d_in[11];
    const float* gak = (const float*)d_in[12];
    const float* bo  = (const float*)d_in[14];
    const float* bao = (const float*)d_in[16];
    float* out = (float*)d_out;

    bf16 *xh, *xl, *qh, *ql, *kh, *kl, *vh, *vl, *ath, *atl, *wh, *wl;
    cudaGetSymbolAddress((void**)&xh,  g_xh);
    cudaGetSymbolAddress((void**)&xl,  g_xl);
    cudaGetSymbolAddress((void**)&qh,  g_qh);
    cudaGetSymbolAddress((void**)&ql,  g_ql);
    cudaGetSymbolAddress((void**)&kh,  g_kh);
    cudaGetSymbolAddress((void**)&kl,  g_kl);
    cudaGetSymbolAddress((void**)&vh,  g_vh);
    cudaGetSymbolAddress((void**)&vl,  g_vl);
    cudaGetSymbolAddress((void**)&ath, g_ath);
    cudaGetSymbolAddress((void**)&atl, g_atl);
    cudaGetSymbolAddress((void**)&wh,  g_wh);
    cudaGetSymbolAddress((void**)&wl,  g_wl);

    cudaFuncSetAttribute(qkv_gemm,     cudaFuncAttributeMaxDynamicSharedMemorySize, SMEMB64);
    cudaFuncSetAttribute(tgemm,        cudaFuncAttributeMaxDynamicSharedMemorySize, SMEMB64);
    cudaFuncSetAttribute(flash_kernel, cudaFuncAttributeMaxDynamicSharedMemorySize, FLASH_SMEM);

    const long WSZ = (long)DMODEL * DMODEL;
    const float scale = 0.088388347648318447f;   // 1/sqrt(128)

    prep_kernel<<<dim3(1024, 9), 256>>>(
        hid, enc,
        (const float*)d_in[3],  (const float*)d_in[4],  (const float*)d_in[5],
        (const float*)d_in[6],  (const float*)d_in[7],  (const float*)d_in[8],
        (const float*)d_in[13], (const float*)d_in[15],
        wh, wl, xh, xl);

    qkv_gemm<<<dim3(QKVP / 128, SEQ_TOT / 64), 256, SMEMB64>>>(
        xh, xl, wh, wl,
        qh, ql, kh, kl, vh, vl,
        gq, gaq, gk, gak, freqs, scale);

    flash_kernel<<<dim3(SEQ_TOT / 128, NHEADS), 256, FLASH_SMEM>>>(
        qh, ql, kh, kl, vh, vl, ath, atl);

    tgemm<<<dim3(24, SEQ_TOT / 64), 256, SMEMB64>>>(
        ath, atl,
        wh + 6 * WSZ, wl + 6 * WSZ, wh + 7 * WSZ, wl + 7 * WSZ,
        out, bo, bao);
}

// round 15
// speedup vs baseline: 1.0749x; 1.0749x over previous
#include <cuda_runtime.h>
#include <cuda_bf16.h>
#include <math.h>
#include <stdint.h>

#define SEQ_TXT 256
#define SEQ_IMG 2048
#define SEQ_TOT 2304
#define DMODEL  3072
#define NHEADS  24
#define DHEAD   128
#define QKVP    (3 * DMODEL)

typedef __nv_bfloat16 bf16;

// bf16 hi/lo pre-split operands (weights kept in natural [k][n] layout)
__device__ bf16 g_xh[SEQ_TOT * DMODEL],  g_xl[SEQ_TOT * DMODEL];
__device__ bf16 g_qh[SEQ_TOT * DMODEL],  g_ql[SEQ_TOT * DMODEL];
__device__ bf16 g_kh[SEQ_TOT * DMODEL],  g_kl[SEQ_TOT * DMODEL];
__device__ bf16 g_vh[SEQ_TOT * DMODEL],  g_vl[SEQ_TOT * DMODEL];   // [seq][d]
__device__ bf16 g_ath[SEQ_TOT * DMODEL], g_atl[SEQ_TOT * DMODEL];
__device__ bf16 g_wh[8][DMODEL * (long)DMODEL];
__device__ bf16 g_wl[8][DMODEL * (long)DMODEL];

__device__ __forceinline__ void bsplit(float x, bf16& h, bf16& l) {
    h = __float2bfloat16_rn(x);
    l = __float2bfloat16_rn(x - __bfloat162float(h));
}
__device__ __forceinline__ uint32_t pack2(bf16 a, bf16 b) {
    __nv_bfloat162 t = __halves2bfloat162(a, b);
    return *(uint32_t*)&t;
}
__device__ __forceinline__ uint32_t cvta_s(const void* p) {
    return (uint32_t)__cvta_generic_to_shared(p);
}

#define MMA_BF16(CV, AV, BV) \
    asm volatile( \
        "mma.sync.aligned.m16n8k16.row.col.f32.bf16.bf16.f32 " \
        "{%0,%1,%2,%3}, {%4,%5,%6,%7}, {%8,%9}, {%0,%1,%2,%3};" \
        : "+f"((CV)[0]), "+f"((CV)[1]), "+f"((CV)[2]), "+f"((CV)[3]) \
        : "r"((AV)[0]), "r"((AV)[1]), "r"((AV)[2]), "r"((AV)[3]), \
          "r"((BV)[0]), "r"((BV)[1]))

#define LDSM_X4(R, ADDR) \
    asm volatile("ldmatrix.sync.aligned.m8n8.x4.shared.b16 {%0,%1,%2,%3}, [%4];" \
        : "=r"((R)[0]), "=r"((R)[1]), "=r"((R)[2]), "=r"((R)[3]) : "r"(ADDR))

#define LDSM_X4_T(R, ADDR) \
    asm volatile("ldmatrix.sync.aligned.m8n8.x4.trans.shared.b16 {%0,%1,%2,%3}, [%4];" \
        : "=r"((R)[0]), "=r"((R)[1]), "=r"((R)[2]), "=r"((R)[3]) : "r"(ADDR))

#define CP_ASYNC16(dst, src) \
    asm volatile("cp.async.cg.shared.global [%0], [%1], 16;" \
        :: "r"(dst), "l"(src) : "memory")
#define CP_COMMIT() asm volatile("cp.async.commit_group;" ::: "memory")
#define CP_WAIT(N)  asm volatile("cp.async.wait_group %0;" :: "n"(N) : "memory")

// Term-outermost mma block (bit-exact per-accumulator order hh->hl->lh)
#define MMA_BLOCK(ACC, AH, AL, BH, BL) \
    do { \
        _Pragma("unroll") \
        for (int mt = 0; mt < 2; mt++) \
            _Pragma("unroll") \
            for (int nt = 0; nt < 8; nt++) \
                MMA_BF16(ACC[mt][nt], AH[mt], (&BH[nt >> 1][(nt & 1) * 2])); \
        _Pragma("unroll") \
        for (int mt = 0; mt < 2; mt++) \
            _Pragma("unroll") \
            for (int nt = 0; nt < 8; nt++) \
                MMA_BF16(ACC[mt][nt], AH[mt], (&BL[nt >> 1][(nt & 1) * 2])); \
        _Pragma("unroll") \
        for (int mt = 0; mt < 2; mt++) \
            _Pragma("unroll") \
            for (int nt = 0; nt < 8; nt++) \
                MMA_BF16(ACC[mt][nt], AL[mt], (&BH[nt >> 1][(nt & 1) * 2])); \
    } while (0)

// A tile: 128 rows x 20 words; B tile: 32 k-rows x 68 words
#define WSTRIDE 20
#define ATWB (128 * WSTRIDE * 4)    // 10240
#define BTWB (32 * 68 * 4)          // 8704
#define STAGE_B (2 * ATWB + 2 * BTWB)   // 37888
#define NSTAGE 3
#define SMEMB_TOTAL (NSTAGE * STAGE_B)  // 113664
#define BOFF_HI (2 * ATWB)
#define BOFF_LO (2 * ATWB + BTWB)

// ===========================================================================
// QKV GEMM + fused epilogue (3-stage cp.async pipeline).
// ===========================================================================
__global__ __launch_bounds__(256, 2) void qkv_gemm(
    const bf16* __restrict__ Ahi, const bf16* __restrict__ Alo,
    const bf16* __restrict__ Wh, const bf16* __restrict__ Wl,
    bf16* __restrict__ qh, bf16* __restrict__ ql,
    bf16* __restrict__ kh, bf16* __restrict__ kl,
    bf16* __restrict__ vh, bf16* __restrict__ vl,
    const float* __restrict__ gq, const float* __restrict__ gaq,
    const float* __restrict__ gk, const float* __restrict__ gak,
    const float* __restrict__ freqs, float qscale)
{
    extern __shared__ uint32_t sm[];
    __shared__ float red[4][8][4][2];

    const bool txt = (int)blockIdx.y < 2;
    const int sec  = blockIdx.x / 24;
    const int col0 = blockIdx.x * 128;
    const int nbase = col0 - sec * DMODEL;
    const long WSZ = (long)DMODEL * DMODEL;
    const bf16* Bh = Wh + (sec + (txt ? 3 : 0)) * WSZ;
    const bf16* Bl = Wl + (sec + (txt ? 3 : 0)) * WSZ;

    const int row0 = blockIdx.y * 128;

    const int tid = threadIdx.x;
    const int lane = tid & 31, wid = tid >> 5;
    const int m_off = (wid & 3) * 32, n_off = (wid >> 2) * 64;
    const int lr = lane >> 2, lc = lane & 3;
    const int mg = wid & 3, gg = wid >> 2;

    const uint32_t sbase = cvta_s(sm);
    const uint32_t aoff = ((m_off + (lane & 15)) * WSTRIDE + ((lane >> 4) & 1) * 4) * 4;
    const uint32_t boff = (lane & 15) * 272 + (n_off + ((lane >> 4) & 1) * 8) * 2;
    const uint32_t MT_OFF = 16 * WSTRIDE * 4;

    const int pr = tid >> 2, pw = (tid & 3) * 4;
    const int br = tid >> 4, bj = tid & 15;

    auto issue = [&](int k0, int buf) {
        uint32_t sb = sbase + buf * STAGE_B;
        #pragma unroll
        for (int p = 0; p < 2; p++) {
            int row = pr + p * 64;
            uint32_t so = (uint32_t)(row * WSTRIDE + pw) * 4;
            long ro = (long)(row0 + row) * DMODEL + k0 + pw * 2;
            CP_ASYNC16(sb + so,        Ahi + ro);
            CP_ASYNC16(sb + ATWB + so, Alo + ro);
        }
        #pragma unroll
        for (int p = 0; p < 2; p++) {
            int r = br + p * 16;
            uint32_t so = (uint32_t)(r * 68 + bj * 4) * 4;
            long co = (long)(k0 + r) * DMODEL + nbase + bj * 8;
            CP_ASYNC16(sb + BOFF_HI + so, Bh + co);
            CP_ASYNC16(sb + BOFF_LO + so, Bl + co);
        }
        CP_COMMIT();
    };

    issue(0, 0);
    issue(32, 1);

    float acc[2][8][4];
    #pragma unroll
    for (int mt = 0; mt < 2; mt++)
        #pragma unroll
        for (int nt = 0; nt < 8; nt++)
            #pragma unroll
            for (int i = 0; i < 4; i++) acc[mt][nt][i] = 0.0f;

    const int nIter = DMODEL >> 5;
    int stg_idx = 0;
    for (int it = 0; it < nIter; ++it) {
        if (it + 2 < nIter) { CP_WAIT(1); } else { CP_WAIT(0); }
        __syncthreads();
        if (it + 2 < nIter) {
            int nb = stg_idx + 2; if (nb >= NSTAGE) nb -= NSTAGE;
            issue((it + 2) * 32, nb);
        }
        const uint32_t stg = sbase + stg_idx * STAGE_B;
        if (++stg_idx == NSTAGE) stg_idx = 0;

        #pragma unroll
        for (int ks = 0; ks < 2; ks++) {
            uint32_t ah[2][4], al[2][4], bh[4][4], bl[4][4];
            #pragma unroll
            for (int mt = 0; mt < 2; mt++) {
                LDSM_X4(ah[mt], stg + aoff + mt * MT_OFF + ks * 32);
                LDSM_X4(al[mt], stg + ATWB + aoff + mt * MT_OFF + ks * 32);
            }
            #pragma unroll
            for (int p = 0; p < 4; p++) {
                LDSM_X4_T(bh[p], stg + BOFF_HI + boff + p * 32 + ks * 4352);
                LDSM_X4_T(bl[p], stg + BOFF_LO + boff + p * 32 + ks * 4352);
            }
            MMA_BLOCK(acc, ah, al, bh, bl);
        }
    }
    __syncthreads();

    if (sec < 2) {
        float ss4[4] = {0.f, 0.f, 0.f, 0.f};
        #pragma unroll
        for (int mt = 0; mt < 2; mt++)
            #pragma unroll
            for (int nt = 0; nt < 8; nt++)
                #pragma unroll
                for (int c = 0; c < 4; c++) {
                    float v = acc[mt][nt][c];
                    ss4[mt * 2 + (c >> 1)] += v * v;
                }
        #pragma unroll
        for (int s = 0; s < 4; s++) {
            ss4[s] += __shfl_xor_sync(0xffffffffu, ss4[s], 1);
            ss4[s] += __shfl_xor_sync(0xffffffffu, ss4[s], 2);
            if (lc == 0) red[mg][lr][s][gg] = ss4[s];
        }
        __syncthreads();

        float rn4[4];
        #pragma unroll
        for (int s = 0; s < 4; s++) {
            float tot = ss4[s] + red[mg][lr][s][gg ^ 1];
            rn4[s] = rsqrtf(tot * (1.0f / 128.0f) + 1e-5f);
        }

        const float* g = (sec == 0) ? (txt ? gaq : gq) : (txt ? gak : gk);
        bf16* oh = (sec == 0) ? qh : kh;
        bf16* ol = (sec == 0) ? ql : kl;
        const float sc = (sec == 0) ? qscale : 1.0f;

        #pragma unroll
        for (int mt = 0; mt < 2; mt++) {
            int r0 = row0 + m_off + mt * 16 + lr;
            #pragma unroll
            for (int nt = 0; nt < 8; nt++) {
                int d = n_off + nt * 8 + lc * 2;
                float g0 = g[d], g1 = g[d + 1];
                {
                    float rn = rn4[mt * 2];
                    float x0 = acc[mt][nt][0] * rn * g0;
                    float x1 = acc[mt][nt][1] * rn * g1;
                    float4 fv = *(const float4*)(freqs + (long)r0 * 256 + (d >> 1) * 4);
                    float o0 = (fv.x * x0 + fv.y * x1) * sc;
                    float o1 = (fv.z * x0 + fv.w * x1) * sc;
                    bf16 h0, l0, h1, l1;
                    bsplit(o0, h0, l0); bsplit(o1, h1, l1);
                    long off = (long)r0 * DMODEL + nbase + d;
                    *(uint32_t*)(oh + off) = pack2(h0, h1);
                    *(uint32_t*)(ol + off) = pack2(l0, l1);
                }
                {
                    float rn = rn4[mt * 2 + 1];
                    float x0 = acc[mt][nt][2] * rn * g0;
                    float x1 = acc[mt][nt][3] * rn * g1;
                    float4 fv = *(const float4*)(freqs + (long)(r0 + 8) * 256 + (d >> 1) * 4);
                    float o0 = (fv.x * x0 + fv.y * x1) * sc;
                    float o1 = (fv.z * x0 + fv.w * x1) * sc;
                    bf16 h0, l0, h1, l1;
                    bsplit(o0, h0, l0); bsplit(o1, h1, l1);
                    long off = (long)(r0 + 8) * DMODEL + nbase + d;
                    *(uint32_t*)(oh + off) = pack2(h0, h1);
                    *(uint32_t*)(ol + off) = pack2(l0, l1);
                }
            }
        }
    } else {
        #pragma unroll
        for (int mt = 0; mt < 2; mt++) {
            int r0 = row0 + m_off + mt * 16 + lr;
            #pragma unroll
            for (int nt = 0; nt < 8; nt++) {
                int d = n_off + nt * 8 + lc * 2;
                bf16 h0, l0, h1, l1;
                bsplit(acc[mt][nt][0], h0, l0);
                bsplit(acc[mt][nt][1], h1, l1);
                long off = (long)r0 * DMODEL + nbase + d;
                *(uint32_t*)(vh + off) = pack2(h0, h1);
                *(uint32_t*)(vl + off) = pack2(l0, l1);
                bsplit(acc[mt][nt][2], h0, l0);
                bsplit(acc[mt][nt][3], h1, l1);
                off = (long)(r0 + 8) * DMODEL + nbase + d;
                *(uint32_t*)(vh + off) = pack2(h0, h1);
                *(uint32_t*)(vl + off) = pack2(l0, l1);
            }
        }
    }
}

// ===========================================================================
// Output-projection GEMM (3-stage pipeline)
// ===========================================================================
__global__ __launch_bounds__(256, 2) void tgemm(
    const bf16* __restrict__ Ahi, const bf16* __restrict__ Alo,
    const bf16* __restrict__ Bhi, const bf16* __restrict__ Blo,
    const bf16* __restrict__ B2hi, const bf16* __restrict__ B2lo,
    float* __restrict__ C,
    const float* __restrict__ bias, const float* __restrict__ bias2)
{
    extern __shared__ uint32_t sm[];

    const bool txt = (int)blockIdx.y < 2;
    const bf16* Bh = txt ? B2hi : Bhi;
    const bf16* Bl = txt ? B2lo : Blo;
    const float* bptr = txt ? bias2 : bias;

    const int row0 = blockIdx.y * 128;
    const int col0 = blockIdx.x * 128;
    const int crow0 = txt ? (SEQ_IMG + row0) : (row0 - SEQ_TXT);

    const int tid = threadIdx.x;
    const int lane = tid & 31, wid = tid >> 5;
    const int m_off = (wid & 3) * 32, n_off = (wid >> 2) * 64;
    const int lr = lane >> 2, lc = lane & 3;

    const uint32_t sbase = cvta_s(sm);
    const uint32_t aoff = ((m_off + (lane & 15)) * WSTRIDE + ((lane >> 4) & 1) * 4) * 4;
    const uint32_t boff = (lane & 15) * 272 + (n_off + ((lane >> 4) & 1) * 8) * 2;
    const uint32_t MT_OFF = 16 * WSTRIDE * 4;

    const int pr = tid >> 2, pw = (tid & 3) * 4;
    const int br = tid >> 4, bj = tid & 15;

    auto issue = [&](int k0, int buf) {
        uint32_t sb = sbase + buf * STAGE_B;
        #pragma unroll
        for (int p = 0; p < 2; p++) {
            int row = pr + p * 64;
            uint32_t so = (uint32_t)(row * WSTRIDE + pw) * 4;
            long ro = (long)(row0 + row) * DMODEL + k0 + pw * 2;
            CP_ASYNC16(sb + so,        Ahi + ro);
            CP_ASYNC16(sb + ATWB + so, Alo + ro);
        }
        #pragma unroll
        for (int p = 0; p < 2; p++) {
            int r = br + p * 16;
            uint32_t so = (uint32_t)(r * 68 + bj * 4) * 4;
            long co = (long)(k0 + r) * DMODEL + col0 + bj * 8;
            CP_ASYNC16(sb + BOFF_HI + so, Bh + co);
            CP_ASYNC16(sb + BOFF_LO + so, Bl + co);
        }
        CP_COMMIT();
    };

    issue(0, 0);
    issue(32, 1);

    float acc[2][8][4];
    #pragma unroll
    for (int mt = 0; mt < 2; mt++)
        #pragma unroll
        for (int nt = 0; nt < 8; nt++)
            #pragma unroll
            for (int i = 0; i < 4; i++) acc[mt][nt][i] = 0.0f;

    const int nIter = DMODEL >> 5;
    int stg_idx = 0;
    for (int it = 0; it < nIter; ++it) {
        if (it + 2 < nIter) { CP_WAIT(1); } else { CP_WAIT(0); }
        __syncthreads();
        if (it + 2 < nIter) {
            int nb = stg_idx + 2; if (nb >= NSTAGE) nb -= NSTAGE;
            issue((it + 2) * 32, nb);
        }
        const uint32_t stg = sbase + stg_idx * STAGE_B;
        if (++stg_idx == NSTAGE) stg_idx = 0;

        #pragma unroll
        for (int ks = 0; ks < 2; ks++) {
            uint32_t ah[2][4], al[2][4], bh[4][4], bl[4][4];
            #pragma unroll
            for (int mt = 0; mt < 2; mt++) {
                LDSM_X4(ah[mt], stg + aoff + mt * MT_OFF + ks * 32);
                LDSM_X4(al[mt], stg + ATWB + aoff + mt * MT_OFF + ks * 32);
            }
            #pragma unroll
            for (int p = 0; p < 4; p++) {
                LDSM_X4_T(bh[p], stg + BOFF_HI + boff + p * 32 + ks * 4352);
                LDSM_X4_T(bl[p], stg + BOFF_LO + boff + p * 32 + ks * 4352);
            }
            MMA_BLOCK(acc, ah, al, bh, bl);
        }
    }

    #pragma unroll
    for (int mt = 0; mt < 2; mt++) {
        #pragma unroll
        for (int nt = 0; nt < 8; nt++) {
            int r0 = crow0 + m_off + mt * 16 + lr;
            int cc = col0 + n_off + nt * 8 + lc * 2;
            float2 v0, v1;
            v0.x = acc[mt][nt][0] + bptr[cc];
            v0.y = acc[mt][nt][1] + bptr[cc + 1];
            v1.x = acc[mt][nt][2] + bptr[cc];
            v1.y = acc[mt][nt][3] + bptr[cc + 1];
            *(float2*)(C + (long)r0 * DMODEL + cc)       = v0;
            *(float2*)(C + (long)(r0 + 8) * DMODEL + cc) = v1;
        }
    }
}

// ===========================================================================
// Flash attention (unchanged from R13)
// ===========================================================================
#define FTW 8704
#define FTWB (FTW * 4)
#define FLASH_SMEM (6 * FTWB)

__global__ __launch_bounds__(256, 1) void flash_kernel(
    const bf16* __restrict__ Qh, const bf16* __restrict__ Ql,
    const bf16* __restrict__ Kh, const bf16* __restrict__ Kl,
    const bf16* __restrict__ Vh, const bf16* __restrict__ Vl,
    bf16* __restrict__ Oh, bf16* __restrict__ Ol)
{
    extern __shared__ uint32_t sm[];
    __shared__ float red[4][8][4][2];

    const int h  = blockIdx.y;
    const int q0 = blockIdx.x * 128;
    const int tid = threadIdx.x;
    const int lane = tid & 31, wid = tid >> 5;
    const int m_off = (wid & 3) * 32, n_off = (wid >> 2) * 64;
    const int lr = lane >> 2, lc = lane & 3;
    const int mg = wid & 3, gg = wid >> 2;

    uint32_t* sPh = sm + 2 * FTW;
    uint32_t* sPl = sm + 3 * FTW;

    const uint32_t sbase = cvta_s(sm);
    const uint32_t aoff = ((m_off + (lane & 15)) * 68 + ((lane >> 4) & 1) * 4) * 4;
    const uint32_t boff = ((n_off + (lane & 7) + ((lane >> 4) & 1) * 8) * 68
                           + ((lane >> 3) & 1) * 4) * 4;
    const uint32_t voff = (lane & 15) * 272 + (n_off + ((lane >> 4) & 1) * 8) * 2;
    const uint32_t MT_OFF = 16 * 68 * 4;

    auto issue_tile = [&](uint32_t dhb, uint32_t dlb,
                          const bf16* gh, const bf16* gl,
                          int rs0, int cs0) {
        #pragma unroll
        for (int i = 0; i < 8; i++) {
            int idx = tid + 256 * i;
            int r = idx >> 4, u = idx & 15;
            long go = (long)(rs0 + r) * DMODEL + cs0 + u * 8;
            uint32_t so = (uint32_t)(r * 68 + u * 4) * 4;
            CP_ASYNC16(dhb + so, gh + go);
            CP_ASYNC16(dlb + so, gl + go);
        }
        CP_COMMIT();
    };

    issue_tile(sbase, sbase + FTWB, Qh, Ql, q0, h * DHEAD);

    float m_i[4], l_i[4], oacc[2][8][4];
    #pragma unroll
    for (int s = 0; s < 4; s++) { m_i[s] = -INFINITY; l_i[s] = 0.0f; }
    #pragma unroll
    for (int mt = 0; mt < 2; mt++)
        #pragma unroll
        for (int nt = 0; nt < 8; nt++)
            #pragma unroll
            for (int c = 0; c < 4; c++) oacc[mt][nt][c] = 0.0f;

    for (int kv = 0; kv < SEQ_TOT / 128; kv++) {
        const int kv0 = kv * 128;
        __syncthreads();
        issue_tile(sbase + 2 * FTWB, sbase + 3 * FTWB, Kh, Kl, kv0, h * DHEAD);
        issue_tile(sbase + 4 * FTWB, sbase + 5 * FTWB, Vh, Vl, kv0, h * DHEAD);
        CP_WAIT(1);
        __syncthreads();

        float sacc[2][8][4];
        #pragma unroll
        for (int mt = 0; mt < 2; mt++)
            #pragma unroll
            for (int nt = 0; nt < 8; nt++)
                #pragma unroll
                for (int c = 0; c < 4; c++) sacc[mt][nt][c] = 0.0f;

        #pragma unroll
        for (int ks = 0; ks < 8; ks++) {
            uint32_t ah[2][4], al[2][4], bh[4][4], bl[4][4];
            #pragma unroll
            for (int mt = 0; mt < 2; mt++) {
                LDSM_X4(ah[mt], sbase + aoff + mt * MT_OFF + ks * 32);
                LDSM_X4(al[mt], sbase + FTWB + aoff + mt * MT_OFF + ks * 32);
            }
            #pragma unroll
            for (int p = 0; p < 4; p++) {
                LDSM_X4(bh[p], sbase + 2 * FTWB + boff + p * MT_OFF + ks * 32);
                LDSM_X4(bl[p], sbase + 3 * FTWB + boff + p * MT_OFF + ks * 32);
            }
            MMA_BLOCK(sacc, ah, al, bh, bl);
        }

        float mx4[4];
        #pragma unroll
        for (int s = 0; s < 4; s++) {
            int mt = s >> 1, c0 = (s & 1) * 2;
            float mx = sacc[mt][0][c0];
            #pragma unroll
            for (int nt = 0; nt < 8; nt++) {
                mx = fmaxf(mx, sacc[mt][nt][c0]);
                mx = fmaxf(mx, sacc[mt][nt][c0 + 1]);
            }
            mx = fmaxf(mx, __shfl_xor_sync(0xffffffffu, mx, 1));
            mx = fmaxf(mx, __shfl_xor_sync(0xffffffffu, mx, 2));
            mx4[s] = mx;
            if (lc == 0) red[mg][lr][s][gg] = mx;
        }
        __syncthreads();

        float a4[4], mnew[4];
        #pragma unroll
        for (int s = 0; s < 4; s++) {
            mnew[s] = fmaxf(m_i[s], fmaxf(mx4[s], red[mg][lr][s][gg ^ 1]));
            a4[s] = __expf(m_i[s] - mnew[s]);
            m_i[s] = mnew[s];
            l_i[s] *= a4[s];
        }

        float rs4[4] = {0.f, 0.f, 0.f, 0.f};
        #pragma unroll
        for (int mt = 0; mt < 2; mt++)
            #pragma unroll
            for (int nt = 0; nt < 8; nt++)
                #pragma unroll
                for (int c = 0; c < 4; c++) {
                    int s = mt * 2 + (c >> 1);
                    float e = __expf(sacc[mt][nt][c] - mnew[s]);
                    sacc[mt][nt][c] = e;
                    rs4[s] += e;
                }
        #pragma unroll
        for (int s = 0; s < 4; s++) {
            rs4[s] += __shfl_xor_sync(0xffffffffu, rs4[s], 1);
            rs4[s] += __shfl_xor_sync(0xffffffffu, rs4[s], 2);
        }
        #pragma unroll
        for (int mt = 0; mt < 2; mt++)
            #pragma unroll
            for (int nt = 0; nt < 8; nt++) {
                oacc[mt][nt][0] *= a4[mt * 2];
                oacc[mt][nt][1] *= a4[mt * 2];
                oacc[mt][nt][2] *= a4[mt * 2 + 1];
                oacc[mt][nt][3] *= a4[mt * 2 + 1];
            }
        __syncthreads();

        #pragma unroll
        for (int s = 0; s < 4; s++)
            if (lc == 0) red[mg][lr][s][gg] = rs4[s];

        #pragma unroll
        for (int mt = 0; mt < 2; mt++)
            #pragma unroll
            for (int nt = 0; nt < 8; nt++) {
                int w = (n_off >> 1) + nt * 4 + lc;
                int o = (m_off + mt * 16 + lr) * 68 + w;
                bf16 h0, l0, h1, l1;
                bsplit(sacc[mt][nt][0], h0, l0);
                bsplit(sacc[mt][nt][1], h1, l1);
                sPh[o] = pack2(h0, h1); sPl[o] = pack2(l0, l1);
                bsplit(sacc[mt][nt][2], h0, l0);
                bsplit(sacc[mt][nt][3], h1, l1);
                sPh[o + 8 * 68] = pack2(h0, h1); sPl[o + 8 * 68] = pack2(l0, l1);
            }
        CP_WAIT(0);
        __syncthreads();

        #pragma unroll
        for (int s = 0; s < 4; s++)
            l_i[s] += rs4[s] + red[mg][lr][s][gg ^ 1];

        #pragma unroll
        for (int ks = 0; ks < 8; ks++) {
            uint32_t ah[2][4], al[2][4], bh[4][4], bl[4][4];
            #pragma unroll
            for (int mt = 0; mt < 2; mt++) {
                LDSM_X4(ah[mt], sbase + 2 * FTWB + aoff + mt * MT_OFF + ks * 32);
                LDSM_X4(al[mt], sbase + 3 * FTWB + aoff + mt * MT_OFF + ks * 32);
            }
            #pragma unroll
            for (int p = 0; p < 4; p++) {
                LDSM_X4_T(bh[p], sbase + 4 * FTWB + voff + p * 32 + ks * 4352);
                LDSM_X4_T(bl[p], sbase + 5 * FTWB + voff + p * 32 + ks * 4352);
            }
            MMA_BLOCK(oacc, ah, al, bh, bl);
        }
    }

    #pragma unroll
    for (int mt = 0; mt < 2; mt++) {
        float i0 = 1.0f / l_i[mt * 2];
        float i1 = 1.0f / l_i[mt * 2 + 1];
        #pragma unroll
        for (int nt = 0; nt < 8; nt++) {
            int col = h * DHEAD + n_off + nt * 8 + lc * 2;
            long r0 = q0 + m_off + mt * 16 + lr;
            bf16 h0, l0, h1, l1;
            bsplit(oacc[mt][nt][0] * i0, h0, l0);
            bsplit(oacc[mt][nt][1] * i0, h1, l1);
            *(uint32_t*)(Oh + r0 * DMODEL + col) = pack2(h0, h1);
            *(uint32_t*)(Ol + r0 * DMODEL + col) = pack2(l0, l1);
            bsplit(oacc[mt][nt][2] * i1, h0, l0);
            bsplit(oacc[mt][nt][3] * i1, h1, l1);
            *(uint32_t*)(Oh + (r0 + 8) * DMODEL + col) = pack2(h0, h1);
            *(uint32_t*)(Ol + (r0 + 8) * DMODEL + col) = pack2(l0, l1);
        }
    }
}

// ===========================================================================
// Prep: pure streaming hi/lo split. y<8 -> weight y; y==8 -> inputs.
// ===========================================================================
__global__ __launch_bounds__(256) void prep_kernel(
    const float* __restrict__ hid, const float* __restrict__ enc,
    const float* W0, const float* W1, const float* W2, const float* W3,
    const float* W4, const float* W5, const float* W6, const float* W7,
    bf16* __restrict__ wh, bf16* __restrict__ wl,
    bf16* __restrict__ xh, bf16* __restrict__ xl)
{
    const int z = blockIdx.y;
    const int tid = threadIdx.x;
    const int NBLK = 1024;

    const float* src;
    bf16 *hi, *lo;
    int n4;
    if (z == 8) {
        n4 = SEQ_TOT * DMODEL / 4;
        src = nullptr; hi = xh; lo = xl;
    } else {
        n4 = DMODEL * DMODEL / 4;
        const float* Ws = W0;
        switch (z) {
            case 1: Ws = W1; break; case 2: Ws = W2; break; case 3: Ws = W3; break;
            case 4: Ws = W4; break; case 5: Ws = W5; break; case 6: Ws = W6; break;
            case 7: Ws = W7; break; default: break;
        }
        src = Ws;
        hi = wh + (long)z * DMODEL * DMODEL;
        lo = wl + (long)z * DMODEL * DMODEL;
    }

    const int TXT4 = SEQ_TXT * DMODEL / 4;
    for (int idx = blockIdx.x * 256 + tid; idx < n4; idx += NBLK * 256) {
        float4 v;
        if (z == 8)
            v = (idx < TXT4) ? ((const float4*)enc)[idx]
                             : ((const float4*)hid)[idx - TXT4];
        else
            v = ((const float4*)src)[idx];
        bf16 h0, l0, h1, l1, h2, l2, h3, l3;
        bsplit(v.x, h0, l0); bsplit(v.y, h1, l1);
        bsplit(v.z, h2, l2); bsplit(v.w, h3, l3);
        ((uint2*)hi)[idx] = make_uint2(pack2(h0, h1), pack2(h2, h3));
        ((uint2*)lo)[idx] = make_uint2(pack2(l0, l1), pack2(l2, l3));
    }
}

// ---------------------------------------------------------------------------
extern "C" void kernel_launch(void* const* d_in, const int* in_sizes, int n_in,
                              void* d_out, int out_size)
{
    const float* hid   = (const float*)d_in[0];
    const float* enc   = (const float*)d_in[1];
    const float* freqs = (const float*)d_in[2];
    const float* gq  = (const float*)d_in[9];
    const float* gk  = (const float*)d_in[10];
    const float* gaq = (const float*)d_in[11];
    const float* gak = (const float*)d_in[12];
    const float* bo  = (const float*)d_in[14];
    const float* bao = (const float*)d_in[16];
    float* out = (float*)d_out;

    bf16 *xh, *xl, *qh, *ql, *kh, *kl, *vh, *vl, *ath, *atl, *wh, *wl;
    cudaGetSymbolAddress((void**)&xh,  g_xh);
    cudaGetSymbolAddress((void**)&xl,  g_xl);
    cudaGetSymbolAddress((void**)&qh,  g_qh);
    cudaGetSymbolAddress((void**)&ql,  g_ql);
    cudaGetSymbolAddress((void**)&kh,  g_kh);
    cudaGetSymbolAddress((void**)&kl,  g_kl);
    cudaGetSymbolAddress((void**)&vh,  g_vh);
    cudaGetSymbolAddress((void**)&vl,  g_vl);
    cudaGetSymbolAddress((void**)&ath, g_ath);
    cudaGetSymbolAddress((void**)&atl, g_atl);
    cudaGetSymbolAddress((void**)&wh,  g_wh);
    cudaGetSymbolAddress((void**)&wl,  g_wl);

    cudaFuncSetAttribute(qkv_gemm,     cudaFuncAttributeMaxDynamicSharedMemorySize, SMEMB_TOTAL);
    cudaFuncSetAttribute(tgemm,        cudaFuncAttributeMaxDynamicSharedMemorySize, SMEMB_TOTAL);
    cudaFuncSetAttribute(flash_kernel, cudaFuncAttributeMaxDynamicSharedMemorySize, FLASH_SMEM);

    const long WSZ = (long)DMODEL * DMODEL;
    const float scale = 0.088388347648318447f;   // 1/sqrt(128)

    prep_kernel<<<dim3(1024, 9), 256>>>(
        hid, enc,
        (const float*)d_in[3],  (const float*)d_in[4],  (const float*)d_in[5],
        (const float*)d_in[6],  (const float*)d_in[7],  (const float*)d_in[8],
        (const float*)d_in[13], (const float*)d_in[15],
        wh, wl, xh, xl);

    qkv_gemm<<<dim3(QKVP / 128, SEQ_TOT / 128), 256, SMEMB_TOTAL>>>(
        xh, xl, wh, wl,
        qh, ql, kh, kl, vh, vl,
        gq, gaq, gk, gak, freqs, scale);

    flash_kernel<<<dim3(SEQ_TOT / 128, NHEADS), 256, FLASH_SMEM>>>(
        qh, ql, kh, kl, vh, vl, ath, atl);

    tgemm<<<dim3(24, SEQ_TOT / 128), 256, SMEMB_TOTAL>>>(
        ath, atl,
        wh + 6 * WSZ, wl + 6 * WSZ, wh + 7 * WSZ, wl + 7 * WSZ,
        out, bo, bao);
}